// round 2
// baseline (speedup 1.0000x reference)
#include <cuda_runtime.h>
#include <math.h>

#define B 8
#define C 192
#define HEADS 4
#define HD 48
#define HGT 128
#define WID 128
#define NPIX 16384
#define CTXD 256
#define HID 510
#define FFN2 1020
#define NSPLIT 32

// ---------------- scratch (static device globals; allocation-free) ----------------
__device__ float g_xn  [B * C    * NPIX];   // layernorm output
__device__ float g_buf1[B * FFN2 * NPIX];   // conv1x1 outputs (qkv 576ch / ffn 1020ch)
__device__ float g_buf2[B * FFN2 * NPIX];   // dwconv outputs
__device__ float g_mid [B * C    * NPIX];   // out_local + out_global
__device__ float g_x2  [B * C    * NPIX];   // x after attention branch
__device__ float g_gelu[B * HID  * NPIX];   // gelu(y1)*y2
__device__ float g_attn_part[B * HEADS * NSPLIT * HD * HD];
__device__ float g_attn[B * HEADS * HD * HD];
__device__ float g_temp [B * HEADS];
__device__ float g_vgate[B * C];
__device__ float g_invq [B * C];
__device__ float g_invk [B * C];

// ---------------- context adapters (tiny) ----------------
__global__ void ctx_kernel(const float* __restrict__ ctx,
                           const float* __restrict__ ta_w1, const float* __restrict__ ta_b1,
                           const float* __restrict__ ta_w2, const float* __restrict__ ta_b2,
                           const float* __restrict__ vg_w,  const float* __restrict__ vg_b,
                           const float* __restrict__ base_temp) {
    __shared__ float sctx[CTXD];
    __shared__ float hid[HD];
    int b = blockIdx.x, t = threadIdx.x;
    sctx[t] = ctx[b * CTXD + t];
    __syncthreads();
    if (t < HD) {
        float s = ta_b1[t];
        for (int k = 0; k < CTXD; k++) s += sctx[k] * ta_w1[t * CTXD + k];
        hid[t] = fmaxf(s, 0.f);
    }
    __syncthreads();
    if (t < HEADS) {
        float s = ta_b2[t];
        for (int k = 0; k < HD; k++) s += hid[k] * ta_w2[t * HD + k];
        float f = 1.f / (1.f + expf(-s)) * 2.f + 0.5f;
        g_temp[b * HEADS + t] = base_temp[t] * f;
    }
    if (t < C) {
        float s = vg_b[t];
        for (int k = 0; k < CTXD; k++) s += sctx[k] * vg_w[t * CTXD + k];
        g_vgate[b * C + t] = 1.f / (1.f + expf(-s));
    }
}

// ---------------- layernorm over channels ----------------
__global__ void ln_kernel(const float* __restrict__ x, const float* __restrict__ w,
                          const float* __restrict__ bias, float* __restrict__ out) {
    int tid = blockIdx.x * 256 + threadIdx.x;   // B*NPIX threads
    int b = tid / NPIX, n = tid % NPIX;
    const float* xp = x + (size_t)b * C * NPIX + n;
    float s = 0.f, ss = 0.f;
    #pragma unroll 4
    for (int c = 0; c < C; c++) { float v = xp[(size_t)c * NPIX]; s += v; ss += v * v; }
    float mu = s * (1.f / C);
    float var = ss * (1.f / C) - mu * mu;
    float rstd = rsqrtf(var + 1e-5f);
    float* op = out + (size_t)b * C * NPIX + n;
    #pragma unroll 4
    for (int c = 0; c < C; c++)
        op[(size_t)c * NPIX] = (xp[(size_t)c * NPIX] - mu) * rstd * w[c] + bias[c];
}

// ---------------- batched conv1x1 GEMM: Y[b,o,n] = sum_c W[o,c] X[b,c,n] (+Res) ----------------
__global__ void gemm_kernel(const float* __restrict__ Wm, const float* __restrict__ X,
                            float* __restrict__ Y, const float* __restrict__ Res,
                            int O, int Cin) {
    __shared__ float sW[16][64];
    __shared__ float sX[16][65];
    int b  = blockIdx.z;
    int o0 = blockIdx.y * 64;
    int n0 = blockIdx.x * 64;
    const float* Xb = X + (size_t)b * Cin * NPIX + n0;
    int tid = threadIdx.x;
    int ty = tid >> 4, tx = tid & 15;
    float acc[4][4];
    #pragma unroll
    for (int i = 0; i < 4; i++)
        #pragma unroll
        for (int j = 0; j < 4; j++) acc[i][j] = 0.f;

    int ktiles = (Cin + 15) >> 4;
    for (int kt = 0; kt < ktiles; kt++) {
        int c0 = kt << 4;
        #pragma unroll
        for (int q = 0; q < 4; q++) {
            int e = tid * 4 + q;
            int o = e >> 4, cc = e & 15;
            float v = 0.f;
            if (o0 + o < O && c0 + cc < Cin) v = Wm[(size_t)(o0 + o) * Cin + c0 + cc];
            sW[cc][o] = v;
        }
        {
            int c = tid >> 4;
            int n = (tid & 15) * 4;
            float4 v = make_float4(0.f, 0.f, 0.f, 0.f);
            if (c0 + c < Cin)
                v = *reinterpret_cast<const float4*>(Xb + (size_t)(c0 + c) * NPIX + n);
            sX[c][n] = v.x; sX[c][n + 1] = v.y; sX[c][n + 2] = v.z; sX[c][n + 3] = v.w;
        }
        __syncthreads();
        #pragma unroll
        for (int kk = 0; kk < 16; kk++) {
            float a[4], bb[4];
            #pragma unroll
            for (int i = 0; i < 4; i++) a[i] = sW[kk][ty * 4 + i];
            #pragma unroll
            for (int j = 0; j < 4; j++) bb[j] = sX[kk][tx * 4 + j];
            #pragma unroll
            for (int i = 0; i < 4; i++)
                #pragma unroll
                for (int j = 0; j < 4; j++) acc[i][j] += a[i] * bb[j];
        }
        __syncthreads();
    }
    #pragma unroll
    for (int i = 0; i < 4; i++) {
        int o = o0 + ty * 4 + i;
        if (o < O) {
            size_t off = (size_t)b * O * NPIX + (size_t)o * NPIX + n0 + tx * 4;
            float4 r = Res ? *reinterpret_cast<const float4*>(Res + off)
                           : make_float4(0.f, 0.f, 0.f, 0.f);
            float4 v = make_float4(acc[i][0] + r.x, acc[i][1] + r.y,
                                   acc[i][2] + r.z, acc[i][3] + r.w);
            *reinterpret_cast<float4*>(Y + off) = v;
        }
    }
}

// ---------------- depthwise 3x3 SAME ----------------
__global__ void dwconv_kernel(const float* __restrict__ in, const float* __restrict__ w,
                              float* __restrict__ out, int CH, int inStrideB, int outStrideB) {
    int idx = blockIdx.x * 256 + threadIdx.x;
    int n = idx & (NPIX - 1);
    int bc = idx >> 14;
    int c = bc % CH, b = bc / CH;
    int y = n >> 7, x = n & 127;
    const float* ip = in + (size_t)b * inStrideB + (size_t)c * NPIX;
    const float* wp = w + c * 9;
    float s = 0.f;
    #pragma unroll
    for (int ky = 0; ky < 3; ky++) {
        int yy = y + ky - 1;
        if (yy < 0 || yy >= HGT) continue;
        #pragma unroll
        for (int kx = 0; kx < 3; kx++) {
            int xx = x + kx - 1;
            if (xx < 0 || xx >= WID) continue;
            s += ip[yy * WID + xx] * wp[ky * 3 + kx];
        }
    }
    out[(size_t)b * outStrideB + (size_t)c * NPIX + n] = s;
}

// ---------------- q/k L2-norm over spatial ----------------
__global__ void norm_kernel() {
    int idx = blockIdx.x;              // 0 .. 2*B*C-1
    int isK = idx >= B * C;
    int lin = isK ? idx - B * C : idx;
    int b = lin / C, c = lin % C;
    const float* p = g_buf2 + (size_t)b * (3 * C) * NPIX + (size_t)((isK ? C : 0) + c) * NPIX;
    float ss = 0.f;
    for (int n = threadIdx.x; n < NPIX; n += 256) { float v = p[n]; ss += v * v; }
    __shared__ float red[256];
    red[threadIdx.x] = ss; __syncthreads();
    for (int s = 128; s > 0; s >>= 1) {
        if (threadIdx.x < s) red[threadIdx.x] += red[threadIdx.x + s];
        __syncthreads();
    }
    if (threadIdx.x == 0) {
        float inv = 1.f / fmaxf(sqrtf(red[0]), 1e-12f);
        (isK ? g_invk : g_invq)[b * C + c] = inv;
    }
}

// ---------------- attention gram partials: split-K, no atomics ----------------
__global__ void attn_part_kernel() {
    __shared__ float sQ[HD][33], sK[HD][33];
    int bh = blockIdx.x / NSPLIT, sp = blockIdx.x % NSPLIT;
    int b = bh / HEADS, h = bh % HEADS;
    const float* qb = g_buf2 + (size_t)b * (3 * C) * NPIX + (size_t)(h * HD) * NPIX;
    const float* kb = qb + (size_t)C * NPIX;
    int t = threadIdx.x;
    int i0 = (t >> 4) * 3, j0 = (t & 15) * 3;
    float acc[3][3];
    #pragma unroll
    for (int a = 0; a < 3; a++)
        #pragma unroll
        for (int c2 = 0; c2 < 3; c2++) acc[a][c2] = 0.f;
    int n0 = sp * (NPIX / NSPLIT);
    for (int ch = 0; ch < NPIX / NSPLIT; ch += 32) {
        for (int e = t; e < HD * 32; e += 256) {
            int i = e >> 5, nn = e & 31;
            sQ[i][nn] = qb[(size_t)i * NPIX + n0 + ch + nn];
            sK[i][nn] = kb[(size_t)i * NPIX + n0 + ch + nn];
        }
        __syncthreads();
        #pragma unroll 4
        for (int kk = 0; kk < 32; kk++) {
            float qa[3], ka[3];
            #pragma unroll
            for (int a = 0; a < 3; a++) { qa[a] = sQ[i0 + a][kk]; ka[a] = sK[j0 + a][kk]; }
            #pragma unroll
            for (int a = 0; a < 3; a++)
                #pragma unroll
                for (int c2 = 0; c2 < 3; c2++) acc[a][c2] += qa[a] * ka[c2];
        }
        __syncthreads();
    }
    float* outp = g_attn_part + (size_t)blockIdx.x * HD * HD;
    #pragma unroll
    for (int a = 0; a < 3; a++)
        #pragma unroll
        for (int c2 = 0; c2 < 3; c2++) outp[(i0 + a) * HD + j0 + c2] = acc[a][c2];
}

// ---------------- softmax + fold norms/scale/temp/vgate ----------------
__global__ void softmax_kernel() {
    __shared__ float row[HD];
    __shared__ float mx, sm;
    int rid = blockIdx.x;          // B*HEADS*HD rows
    int i  = rid % HD;
    int bh = rid / HD;
    int b = bh / HEADS, h = bh % HEADS;
    int t = threadIdx.x;           // 64
    const float scale = 0.14433756729740643f;   // 48^-0.5
    if (t < HD) {
        float s = 0.f;
        const float* pp = g_attn_part + (size_t)bh * NSPLIT * HD * HD + i * HD + t;
        for (int sp = 0; sp < NSPLIT; sp++) s += pp[(size_t)sp * HD * HD];
        row[t] = s * g_invq[b * C + h * HD + i] * g_invk[b * C + h * HD + t]
                   * scale * g_temp[b * HEADS + h];
    }
    __syncthreads();
    if (t == 0) { float m = -1e30f; for (int j = 0; j < HD; j++) m = fmaxf(m, row[j]); mx = m; }
    __syncthreads();
    if (t < HD) row[t] = expf(row[t] - mx);
    __syncthreads();
    if (t == 0) { float s2 = 0.f; for (int j = 0; j < HD; j++) s2 += row[j]; sm = s2; }
    __syncthreads();
    if (t < HD)
        g_attn[(size_t)bh * HD * HD + i * HD + t] = row[t] / sm * g_vgate[b * C + h * HD + t];
}

// ---------------- out_global = attn @ v, accumulated onto out_local in g_mid ----------------
__global__ void og_kernel() {
    __shared__ float sA[HD * HD];
    __shared__ float sV[HD][65];
    int bh = blockIdx.y;
    int b = bh / HEADS, h = bh % HEADS;
    int n0 = blockIdx.x * 64;
    const float* vb = g_buf2 + (size_t)b * (3 * C) * NPIX + (size_t)(2 * C + h * HD) * NPIX;
    int t = threadIdx.x;
    for (int e = t; e < HD * HD; e += 256) sA[e] = g_attn[(size_t)bh * HD * HD + e];
    for (int e = t; e < HD * 64; e += 256) {
        int j = e >> 6, n = e & 63;
        sV[j][n] = vb[(size_t)j * NPIX + n0 + n];
    }
    __syncthreads();
    int i0 = (t >> 4) * 3;
    int nl = (t & 15) * 4;
    float acc[3][4];
    #pragma unroll
    for (int a = 0; a < 3; a++)
        #pragma unroll
        for (int q = 0; q < 4; q++) acc[a][q] = 0.f;
    #pragma unroll 4
    for (int j = 0; j < HD; j++) {
        float vv[4];
        #pragma unroll
        for (int q = 0; q < 4; q++) vv[q] = sV[j][nl + q];
        #pragma unroll
        for (int a = 0; a < 3; a++) {
            float aa = sA[(i0 + a) * HD + j];
            #pragma unroll
            for (int q = 0; q < 4; q++) acc[a][q] += aa * vv[q];
        }
    }
    float* op = g_mid + (size_t)b * C * NPIX + (size_t)(h * HD) * NPIX + n0;
    #pragma unroll
    for (int a = 0; a < 3; a++)
        #pragma unroll
        for (int q = 0; q < 4; q++)
            op[(size_t)(i0 + a) * NPIX + nl + q] += acc[a][q];
}

// ---------------- gelu(y1) * y2 ----------------
__global__ void gelu_kernel() {
    int idx = blockIdx.x * 256 + threadIdx.x;     // B*HID*NPIX total
    int b = idx / (HID * NPIX);
    int rem = idx % (HID * NPIX);
    int ch = rem / NPIX, nn = rem % NPIX;
    const float* base = g_buf2 + (size_t)b * FFN2 * NPIX;
    float y1 = base[(size_t)ch * NPIX + nn];
    float y2 = base[(size_t)(ch + HID) * NPIX + nn];
    float g = 0.5f * y1 * (1.f + erff(y1 * 0.70710678118654752f));
    g_gelu[(size_t)idx] = g * y2;
}

// ---------------- launch ----------------
extern "C" void kernel_launch(void* const* d_in, const int* in_sizes, int n_in,
                              void* d_out, int out_size) {
    const float* x        = (const float*)d_in[0];
    const float* ctx      = (const float*)d_in[1];
    const float* ln1_w    = (const float*)d_in[2];
    const float* ln1_b    = (const float*)d_in[3];
    const float* ln2_w    = (const float*)d_in[4];
    const float* ln2_b    = (const float*)d_in[5];
    const float* w_qkv    = (const float*)d_in[6];
    const float* w_qkv_dw = (const float*)d_in[7];
    const float* w_proj   = (const float*)d_in[8];
    const float* base_temp= (const float*)d_in[9];
    const float* ta_w1    = (const float*)d_in[10];
    const float* ta_b1    = (const float*)d_in[11];
    const float* ta_w2    = (const float*)d_in[12];
    const float* ta_b2    = (const float*)d_in[13];
    const float* vg_w     = (const float*)d_in[14];
    const float* vg_b     = (const float*)d_in[15];
    const float* w_local  = (const float*)d_in[16];
    const float* w_ffn_in = (const float*)d_in[17];
    const float* w_ffn_dw = (const float*)d_in[18];
    const float* w_ffn_out= (const float*)d_in[19];
    float* out = (float*)d_out;

    float *p_xn, *p_buf1, *p_buf2, *p_mid, *p_x2, *p_gelu;
    cudaGetSymbolAddress((void**)&p_xn,   g_xn);
    cudaGetSymbolAddress((void**)&p_buf1, g_buf1);
    cudaGetSymbolAddress((void**)&p_buf2, g_buf2);
    cudaGetSymbolAddress((void**)&p_mid,  g_mid);
    cudaGetSymbolAddress((void**)&p_x2,   g_x2);
    cudaGetSymbolAddress((void**)&p_gelu, g_gelu);

    // context adapters
    ctx_kernel<<<B, 256>>>(ctx, ta_w1, ta_b1, ta_w2, ta_b2, vg_w, vg_b, base_temp);
    // LN1
    ln_kernel<<<(B * NPIX) / 256, 256>>>(x, ln1_w, ln1_b, p_xn);
    // qkv conv1x1 (576 x 192)
    gemm_kernel<<<dim3(NPIX / 64, (3 * C + 63) / 64, B), 256>>>(w_qkv, p_xn, p_buf1, nullptr, 3 * C, C);
    // qkv dwconv
    dwconv_kernel<<<(B * 3 * C * NPIX) / 256, 256>>>(p_buf1, w_qkv_dw, p_buf2, 3 * C,
                                                     3 * C * NPIX, 3 * C * NPIX);
    // q/k norms
    norm_kernel<<<2 * B * C, 256>>>();
    // attention gram partials + softmax
    attn_part_kernel<<<B * HEADS * NSPLIT, 256>>>();
    softmax_kernel<<<B * HEADS * HD, 64>>>();
    // out_local into g_mid, then out_global accumulated on top
    dwconv_kernel<<<(B * C * NPIX) / 256, 256>>>(p_buf2 + (size_t)2 * C * NPIX, w_local, p_mid,
                                                 C, 3 * C * NPIX, C * NPIX);
    og_kernel<<<dim3(NPIX / 64, B * HEADS), 256>>>();
    // proj conv1x1 + residual(x)  -> g_x2
    gemm_kernel<<<dim3(NPIX / 64, C / 64, B), 256>>>(w_proj, p_mid, p_x2, x, C, C);
    // LN2
    ln_kernel<<<(B * NPIX) / 256, 256>>>(p_x2, ln2_w, ln2_b, p_xn);
    // ffn_in conv1x1 (1020 x 192)
    gemm_kernel<<<dim3(NPIX / 64, (FFN2 + 63) / 64, B), 256>>>(w_ffn_in, p_xn, p_buf1, nullptr, FFN2, C);
    // ffn dwconv
    dwconv_kernel<<<(B * FFN2 * NPIX) / 256, 256>>>(p_buf1, w_ffn_dw, p_buf2, FFN2,
                                                    FFN2 * NPIX, FFN2 * NPIX);
    // gelu gate
    gelu_kernel<<<(B * HID * NPIX) / 256, 256>>>();
    // ffn_out conv1x1 (192 x 510) + residual(g_x2) -> d_out
    gemm_kernel<<<dim3(NPIX / 64, C / 64, B), 256>>>(w_ffn_out, p_gelu, out, p_x2, C, HID);
}

// round 3
// speedup vs baseline: 2.1781x; 2.1781x over previous
#include <cuda_runtime.h>
#include <math.h>

#define B 8
#define C 192
#define HEADS 4
#define HD 48
#define HGT 128
#define WID 128
#define NPIX 16384
#define CTXD 256
#define HID 510
#define FFN2 1020
#define NSPLIT 32

// ---------------- scratch (static device globals; allocation-free) ----------------
__device__ float g_xn  [B * C    * NPIX];   // layernorm output
__device__ float g_buf1[B * FFN2 * NPIX];   // conv1x1 outputs (qkv 576ch / ffn 1020ch)
__device__ float g_buf2[B * 3*C  * NPIX];   // qkv dwconv output
__device__ float g_mid [B * C    * NPIX];   // out_local + out_global
__device__ float g_x2  [B * C    * NPIX];   // x after attention branch
__device__ float g_gelu[B * HID  * NPIX];   // gelu(y1)*y2
__device__ float g_attn_part[B * HEADS * NSPLIT * HD * HD];
__device__ float g_attn[B * HEADS * HD * HD];
__device__ float g_temp [B * HEADS];
__device__ float g_vgate[B * C];
__device__ float g_invq [B * C];
__device__ float g_invk [B * C];

// ---------------- tf32 helpers ----------------
__device__ __forceinline__ unsigned f2tf32(float f) {
    unsigned u; asm("cvt.rna.tf32.f32 %0, %1;" : "=r"(u) : "f"(f)); return u;
}
__device__ __forceinline__ void mma_tf32(float* d, const unsigned* a, const unsigned* b) {
    asm volatile(
        "mma.sync.aligned.m16n8k8.row.col.f32.tf32.tf32.f32 "
        "{%0,%1,%2,%3}, {%4,%5,%6,%7}, {%8,%9}, {%0,%1,%2,%3};\n"
        : "+f"(d[0]), "+f"(d[1]), "+f"(d[2]), "+f"(d[3])
        : "r"(a[0]), "r"(a[1]), "r"(a[2]), "r"(a[3]), "r"(b[0]), "r"(b[1]));
}

// ---------------- context adapters (tiny) ----------------
__global__ void ctx_kernel(const float* __restrict__ ctx,
                           const float* __restrict__ ta_w1, const float* __restrict__ ta_b1,
                           const float* __restrict__ ta_w2, const float* __restrict__ ta_b2,
                           const float* __restrict__ vg_w,  const float* __restrict__ vg_b,
                           const float* __restrict__ base_temp) {
    __shared__ float sctx[CTXD];
    __shared__ float hid[HD];
    int b = blockIdx.x, t = threadIdx.x;
    sctx[t] = ctx[b * CTXD + t];
    __syncthreads();
    if (t < HD) {
        float s = ta_b1[t];
        for (int k = 0; k < CTXD; k++) s += sctx[k] * ta_w1[t * CTXD + k];
        hid[t] = fmaxf(s, 0.f);
    }
    __syncthreads();
    if (t < HEADS) {
        float s = ta_b2[t];
        for (int k = 0; k < HD; k++) s += hid[k] * ta_w2[t * HD + k];
        float f = 1.f / (1.f + expf(-s)) * 2.f + 0.5f;
        g_temp[b * HEADS + t] = base_temp[t] * f;
    }
    if (t < C) {
        float s = vg_b[t];
        for (int k = 0; k < CTXD; k++) s += sctx[k] * vg_w[t * CTXD + k];
        g_vgate[b * C + t] = 1.f / (1.f + expf(-s));
    }
}

// ---------------- layernorm over channels ----------------
__global__ void ln_kernel(const float* __restrict__ x, const float* __restrict__ w,
                          const float* __restrict__ bias, float* __restrict__ out) {
    int tid = blockIdx.x * 256 + threadIdx.x;   // B*NPIX threads
    int b = tid / NPIX, n = tid % NPIX;
    const float* xp = x + (size_t)b * C * NPIX + n;
    float s = 0.f, ss = 0.f;
    #pragma unroll 4
    for (int c = 0; c < C; c++) { float v = xp[(size_t)c * NPIX]; s += v; ss += v * v; }
    float mu = s * (1.f / C);
    float var = ss * (1.f / C) - mu * mu;
    float rstd = rsqrtf(var + 1e-5f);
    float* op = out + (size_t)b * C * NPIX + n;
    #pragma unroll 4
    for (int c = 0; c < C; c++)
        op[(size_t)c * NPIX] = (xp[(size_t)c * NPIX] - mu) * rstd * w[c] + bias[c];
}

// ---------------- tf32 tensor-core conv1x1 GEMM ----------------
// Y[b,o,n] = sum_c W[o,c] X[b,c,n] (+Res)
// Block: 64(O) x 128(n) x 16(k). 8 warps as 2x4, each 32x32 via 2x4 m16n8k8.
__global__ void __launch_bounds__(256) mma_gemm(const float* __restrict__ Wm,
                                                const float* __restrict__ X,
                                                float* __restrict__ Y,
                                                const float* __restrict__ Res,
                                                int O, int Cin) {
    __shared__ unsigned sA[64][20];    // [m][k], pad to 20 (banks distinct for frag loads)
    __shared__ unsigned sB[16][136];   // [k][n], pad to 136

    int b  = blockIdx.z;
    int o0 = blockIdx.y * 64;
    int n0 = blockIdx.x * 128;
    const float* Xb = X + (size_t)b * Cin * NPIX + n0;

    int tid  = threadIdx.x;
    int warp = tid >> 5, lane = tid & 31;
    int wm = warp >> 2, wn = warp & 3;       // 2 x 4 warp grid
    int mrow = lane >> 2, kq = lane & 3;

    float acc[2][4][4];
    #pragma unroll
    for (int mt = 0; mt < 2; mt++)
        #pragma unroll
        for (int nt = 0; nt < 4; nt++)
            #pragma unroll
            for (int q = 0; q < 4; q++) acc[mt][nt][q] = 0.f;

    // global->reg staging
    int lo  = tid >> 2;           // o within tile (0..63)
    int lc4 = (tid & 3) * 4;      // k offset {0,4,8,12}
    float wv[4];
    float xv[8];

    int ktiles = (Cin + 15) >> 4;

    auto LOADG = [&](int c0) {
        #pragma unroll
        for (int j = 0; j < 4; j++) {
            int o = o0 + lo, c = c0 + lc4 + j;
            wv[j] = (o < O && c < Cin) ? Wm[(size_t)o * Cin + c] : 0.f;
        }
        #pragma unroll
        for (int i = 0; i < 2; i++) {
            int e = tid + i * 256;
            int c = c0 + (e >> 5);
            int n4 = (e & 31) * 4;
            if (c < Cin) {
                float4 v = *reinterpret_cast<const float4*>(Xb + (size_t)c * NPIX + n4);
                xv[i * 4 + 0] = v.x; xv[i * 4 + 1] = v.y; xv[i * 4 + 2] = v.z; xv[i * 4 + 3] = v.w;
            } else {
                xv[i * 4 + 0] = xv[i * 4 + 1] = xv[i * 4 + 2] = xv[i * 4 + 3] = 0.f;
            }
        }
    };
    auto STORES = [&]() {
        #pragma unroll
        for (int j = 0; j < 4; j++) sA[lo][lc4 + j] = f2tf32(wv[j]);
        #pragma unroll
        for (int i = 0; i < 2; i++) {
            int e = tid + i * 256;
            int kk = e >> 5;
            int n4 = (e & 31) * 4;
            #pragma unroll
            for (int j = 0; j < 4; j++) sB[kk][n4 + j] = f2tf32(xv[i * 4 + j]);
        }
    };

    LOADG(0);
    for (int kt = 0; kt < ktiles; kt++) {
        __syncthreads();
        STORES();
        __syncthreads();
        if (kt + 1 < ktiles) LOADG((kt + 1) * 16);

        #pragma unroll
        for (int ks = 0; ks < 2; ks++) {
            const int k0 = ks * 8;
            unsigned afr[2][4], bfr[4][2];
            #pragma unroll
            for (int mt = 0; mt < 2; mt++) {
                int m = wm * 32 + mt * 16 + mrow;
                afr[mt][0] = sA[m    ][k0 + kq];
                afr[mt][1] = sA[m + 8][k0 + kq];
                afr[mt][2] = sA[m    ][k0 + kq + 4];
                afr[mt][3] = sA[m + 8][k0 + kq + 4];
            }
            #pragma unroll
            for (int nt = 0; nt < 4; nt++) {
                int n = wn * 32 + nt * 8 + mrow;
                bfr[nt][0] = sB[k0 + kq    ][n];
                bfr[nt][1] = sB[k0 + kq + 4][n];
            }
            #pragma unroll
            for (int mt = 0; mt < 2; mt++)
                #pragma unroll
                for (int nt = 0; nt < 4; nt++)
                    mma_tf32(acc[mt][nt], afr[mt], bfr[nt]);
        }
    }

    // epilogue: c0,c1 -> (row, 2kq..2kq+1), c2,c3 -> (row+8, ...)
    size_t base = (size_t)b * O * NPIX;
    #pragma unroll
    for (int mt = 0; mt < 2; mt++) {
        #pragma unroll
        for (int nt = 0; nt < 4; nt++) {
            int ncol = n0 + wn * 32 + nt * 8 + 2 * kq;
            int r0 = o0 + wm * 32 + mt * 16 + mrow;
            if (r0 < O) {
                size_t off = base + (size_t)r0 * NPIX + ncol;
                float2 rr = Res ? *reinterpret_cast<const float2*>(Res + off)
                                : make_float2(0.f, 0.f);
                float2 v = make_float2(acc[mt][nt][0] + rr.x, acc[mt][nt][1] + rr.y);
                *reinterpret_cast<float2*>(Y + off) = v;
            }
            int r1 = r0 + 8;
            if (r1 < O) {
                size_t off = base + (size_t)r1 * NPIX + ncol;
                float2 rr = Res ? *reinterpret_cast<const float2*>(Res + off)
                                : make_float2(0.f, 0.f);
                float2 v = make_float2(acc[mt][nt][2] + rr.x, acc[mt][nt][3] + rr.y);
                *reinterpret_cast<float2*>(Y + off) = v;
            }
        }
    }
}

// ---------------- depthwise 3x3 SAME ----------------
__global__ void dwconv_kernel(const float* __restrict__ in, const float* __restrict__ w,
                              float* __restrict__ out, int CH, int inStrideB, int outStrideB) {
    int idx = blockIdx.x * 256 + threadIdx.x;
    int n = idx & (NPIX - 1);
    int bc = idx >> 14;
    int c = bc % CH, b = bc / CH;
    int y = n >> 7, x = n & 127;
    const float* ip = in + (size_t)b * inStrideB + (size_t)c * NPIX;
    const float* wp = w + c * 9;
    float s = 0.f;
    #pragma unroll
    for (int ky = 0; ky < 3; ky++) {
        int yy = y + ky - 1;
        if (yy < 0 || yy >= HGT) continue;
        #pragma unroll
        for (int kx = 0; kx < 3; kx++) {
            int xx = x + kx - 1;
            if (xx < 0 || xx >= WID) continue;
            s += ip[yy * WID + xx] * wp[ky * 3 + kx];
        }
    }
    out[(size_t)b * outStrideB + (size_t)c * NPIX + n] = s;
}

// ---------------- fused FFN dwconv + gelu gate ----------------
__device__ __forceinline__ float dw3x3(const float* __restrict__ ip, const float* __restrict__ wp,
                                       int y, int x) {
    float s = 0.f;
    #pragma unroll
    for (int ky = 0; ky < 3; ky++) {
        int yy = y + ky - 1;
        if (yy < 0 || yy >= HGT) continue;
        #pragma unroll
        for (int kx = 0; kx < 3; kx++) {
            int xx = x + kx - 1;
            if (xx < 0 || xx >= WID) continue;
            s += ip[yy * WID + xx] * wp[ky * 3 + kx];
        }
    }
    return s;
}

__global__ void dwgelu_kernel(const float* __restrict__ in, const float* __restrict__ w,
                              float* __restrict__ outg) {
    int idx = blockIdx.x * 256 + threadIdx.x;     // B*HID*NPIX threads
    int n = idx & (NPIX - 1);
    int bc = idx >> 14;
    int c = bc % HID, b = bc / HID;
    int y = n >> 7, x = n & 127;
    const float* base = in + (size_t)b * FFN2 * NPIX;
    float y1 = dw3x3(base + (size_t)c * NPIX, w + c * 9, y, x);
    float y2 = dw3x3(base + (size_t)(c + HID) * NPIX, w + (c + HID) * 9, y, x);
    float g = 0.5f * y1 * (1.f + erff(y1 * 0.70710678118654752f));
    outg[(size_t)b * HID * NPIX + (size_t)c * NPIX + n] = g * y2;
}

// ---------------- q/k L2-norm over spatial ----------------
__global__ void norm_kernel() {
    int idx = blockIdx.x;              // 0 .. 2*B*C-1
    int isK = idx >= B * C;
    int lin = isK ? idx - B * C : idx;
    int b = lin / C, c = lin % C;
    const float* p = g_buf2 + (size_t)b * (3 * C) * NPIX + (size_t)((isK ? C : 0) + c) * NPIX;
    float ss = 0.f;
    for (int n = threadIdx.x; n < NPIX; n += 256) { float v = p[n]; ss += v * v; }
    __shared__ float red[256];
    red[threadIdx.x] = ss; __syncthreads();
    for (int s = 128; s > 0; s >>= 1) {
        if (threadIdx.x < s) red[threadIdx.x] += red[threadIdx.x + s];
        __syncthreads();
    }
    if (threadIdx.x == 0) {
        float inv = 1.f / fmaxf(sqrtf(red[0]), 1e-12f);
        (isK ? g_invk : g_invq)[b * C + c] = inv;
    }
}

// ---------------- attention gram partials: split-K, no atomics ----------------
__global__ void attn_part_kernel() {
    __shared__ float sQ[HD][33], sK[HD][33];
    int bh = blockIdx.x / NSPLIT, sp = blockIdx.x % NSPLIT;
    int b = bh / HEADS, h = bh % HEADS;
    const float* qb = g_buf2 + (size_t)b * (3 * C) * NPIX + (size_t)(h * HD) * NPIX;
    const float* kb = qb + (size_t)C * NPIX;
    int t = threadIdx.x;
    int i0 = (t >> 4) * 3, j0 = (t & 15) * 3;
    float acc[3][3];
    #pragma unroll
    for (int a = 0; a < 3; a++)
        #pragma unroll
        for (int c2 = 0; c2 < 3; c2++) acc[a][c2] = 0.f;
    int n0 = sp * (NPIX / NSPLIT);
    for (int ch = 0; ch < NPIX / NSPLIT; ch += 32) {
        for (int e = t; e < HD * 32; e += 256) {
            int i = e >> 5, nn = e & 31;
            sQ[i][nn] = qb[(size_t)i * NPIX + n0 + ch + nn];
            sK[i][nn] = kb[(size_t)i * NPIX + n0 + ch + nn];
        }
        __syncthreads();
        #pragma unroll 4
        for (int kk = 0; kk < 32; kk++) {
            float qa[3], ka[3];
            #pragma unroll
            for (int a = 0; a < 3; a++) { qa[a] = sQ[i0 + a][kk]; ka[a] = sK[j0 + a][kk]; }
            #pragma unroll
            for (int a = 0; a < 3; a++)
                #pragma unroll
                for (int c2 = 0; c2 < 3; c2++) acc[a][c2] += qa[a] * ka[c2];
        }
        __syncthreads();
    }
    float* outp = g_attn_part + (size_t)blockIdx.x * HD * HD;
    #pragma unroll
    for (int a = 0; a < 3; a++)
        #pragma unroll
        for (int c2 = 0; c2 < 3; c2++) outp[(i0 + a) * HD + j0 + c2] = acc[a][c2];
}

// ---------------- softmax + fold norms/scale/temp/vgate ----------------
__global__ void softmax_kernel() {
    __shared__ float row[HD];
    __shared__ float mx, sm;
    int rid = blockIdx.x;          // B*HEADS*HD rows
    int i  = rid % HD;
    int bh = rid / HD;
    int b = bh / HEADS, h = bh % HEADS;
    int t = threadIdx.x;           // 64
    const float scale = 0.14433756729740643f;   // 48^-0.5
    if (t < HD) {
        float s = 0.f;
        const float* pp = g_attn_part + (size_t)bh * NSPLIT * HD * HD + i * HD + t;
        for (int sp = 0; sp < NSPLIT; sp++) s += pp[(size_t)sp * HD * HD];
        row[t] = s * g_invq[b * C + h * HD + i] * g_invk[b * C + h * HD + t]
                   * scale * g_temp[b * HEADS + h];
    }
    __syncthreads();
    if (t == 0) { float m = -1e30f; for (int j = 0; j < HD; j++) m = fmaxf(m, row[j]); mx = m; }
    __syncthreads();
    if (t < HD) row[t] = expf(row[t] - mx);
    __syncthreads();
    if (t == 0) { float s2 = 0.f; for (int j = 0; j < HD; j++) s2 += row[j]; sm = s2; }
    __syncthreads();
    if (t < HD)
        g_attn[(size_t)bh * HD * HD + i * HD + t] = row[t] / sm * g_vgate[b * C + h * HD + t];
}

// ---------------- out_global = attn @ v, accumulated onto out_local in g_mid ----------------
__global__ void og_kernel() {
    __shared__ float sA[HD * HD];
    __shared__ float sV[HD][65];
    int bh = blockIdx.y;
    int b = bh / HEADS, h = bh % HEADS;
    int n0 = blockIdx.x * 64;
    const float* vb = g_buf2 + (size_t)b * (3 * C) * NPIX + (size_t)(2 * C + h * HD) * NPIX;
    int t = threadIdx.x;
    for (int e = t; e < HD * HD; e += 256) sA[e] = g_attn[(size_t)bh * HD * HD + e];
    for (int e = t; e < HD * 64; e += 256) {
        int j = e >> 6, n = e & 63;
        sV[j][n] = vb[(size_t)j * NPIX + n0 + n];
    }
    __syncthreads();
    int i0 = (t >> 4) * 3;
    int nl = (t & 15) * 4;
    float acc[3][4];
    #pragma unroll
    for (int a = 0; a < 3; a++)
        #pragma unroll
        for (int q = 0; q < 4; q++) acc[a][q] = 0.f;
    #pragma unroll 4
    for (int j = 0; j < HD; j++) {
        float vv[4];
        #pragma unroll
        for (int q = 0; q < 4; q++) vv[q] = sV[j][nl + q];
        #pragma unroll
        for (int a = 0; a < 3; a++) {
            float aa = sA[(i0 + a) * HD + j];
            #pragma unroll
            for (int q = 0; q < 4; q++) acc[a][q] += aa * vv[q];
        }
    }
    float* op = g_mid + (size_t)b * C * NPIX + (size_t)(h * HD) * NPIX + n0;
    #pragma unroll
    for (int a = 0; a < 3; a++)
        #pragma unroll
        for (int q = 0; q < 4; q++)
            op[(size_t)(i0 + a) * NPIX + nl + q] += acc[a][q];
}

// ---------------- launch ----------------
extern "C" void kernel_launch(void* const* d_in, const int* in_sizes, int n_in,
                              void* d_out, int out_size) {
    const float* x        = (const float*)d_in[0];
    const float* ctx      = (const float*)d_in[1];
    const float* ln1_w    = (const float*)d_in[2];
    const float* ln1_b    = (const float*)d_in[3];
    const float* ln2_w    = (const float*)d_in[4];
    const float* ln2_b    = (const float*)d_in[5];
    const float* w_qkv    = (const float*)d_in[6];
    const float* w_qkv_dw = (const float*)d_in[7];
    const float* w_proj   = (const float*)d_in[8];
    const float* base_temp= (const float*)d_in[9];
    const float* ta_w1    = (const float*)d_in[10];
    const float* ta_b1    = (const float*)d_in[11];
    const float* ta_w2    = (const float*)d_in[12];
    const float* ta_b2    = (const float*)d_in[13];
    const float* vg_w     = (const float*)d_in[14];
    const float* vg_b     = (const float*)d_in[15];
    const float* w_local  = (const float*)d_in[16];
    const float* w_ffn_in = (const float*)d_in[17];
    const float* w_ffn_dw = (const float*)d_in[18];
    const float* w_ffn_out= (const float*)d_in[19];
    float* out = (float*)d_out;

    float *p_xn, *p_buf1, *p_buf2, *p_mid, *p_x2, *p_gelu;
    cudaGetSymbolAddress((void**)&p_xn,   g_xn);
    cudaGetSymbolAddress((void**)&p_buf1, g_buf1);
    cudaGetSymbolAddress((void**)&p_buf2, g_buf2);
    cudaGetSymbolAddress((void**)&p_mid,  g_mid);
    cudaGetSymbolAddress((void**)&p_x2,   g_x2);
    cudaGetSymbolAddress((void**)&p_gelu, g_gelu);

    // context adapters
    ctx_kernel<<<B, 256>>>(ctx, ta_w1, ta_b1, ta_w2, ta_b2, vg_w, vg_b, base_temp);
    // LN1
    ln_kernel<<<(B * NPIX) / 256, 256>>>(x, ln1_w, ln1_b, p_xn);
    // qkv conv1x1 (576 x 192) -> buf1
    mma_gemm<<<dim3(NPIX / 128, (3 * C + 63) / 64, B), 256>>>(w_qkv, p_xn, p_buf1, nullptr, 3 * C, C);
    // qkv dwconv -> buf2
    dwconv_kernel<<<(B * 3 * C * NPIX) / 256, 256>>>(p_buf1, w_qkv_dw, p_buf2, 3 * C,
                                                     3 * C * NPIX, 3 * C * NPIX);
    // q/k norms
    norm_kernel<<<2 * B * C, 256>>>();
    // attention gram partials + softmax
    attn_part_kernel<<<B * HEADS * NSPLIT, 256>>>();
    softmax_kernel<<<B * HEADS * HD, 64>>>();
    // out_local into g_mid, then out_global accumulated on top
    dwconv_kernel<<<(B * C * NPIX) / 256, 256>>>(p_buf2 + (size_t)2 * C * NPIX, w_local, p_mid,
                                                 C, 3 * C * NPIX, C * NPIX);
    og_kernel<<<dim3(NPIX / 64, B * HEADS), 256>>>();
    // proj conv1x1 + residual(x)  -> g_x2
    mma_gemm<<<dim3(NPIX / 128, C / 64, B), 256>>>(w_proj, p_mid, p_x2, x, C, C);
    // LN2
    ln_kernel<<<(B * NPIX) / 256, 256>>>(p_x2, ln2_w, ln2_b, p_xn);
    // ffn_in conv1x1 (1020 x 192) -> buf1
    mma_gemm<<<dim3(NPIX / 128, (FFN2 + 63) / 64, B), 256>>>(w_ffn_in, p_xn, p_buf1, nullptr, FFN2, C);
    // fused ffn dwconv + gelu gate -> g_gelu
    dwgelu_kernel<<<(B * HID * NPIX) / 256, 256>>>(p_buf1, w_ffn_dw, p_gelu);
    // ffn_out conv1x1 (192 x 510) + residual(g_x2) -> d_out
    mma_gemm<<<dim3(NPIX / 128, C / 64, B), 256>>>(w_ffn_out, p_gelu, out, p_x2, C, HID);
}

// round 4
// speedup vs baseline: 3.2534x; 1.4937x over previous
#include <cuda_runtime.h>
#include <math.h>

#define B 8
#define C 192
#define HEADS 4
#define HD 48
#define HGT 128
#define WID 128
#define NPIX 16384
#define CTXD 256
#define HID 510
#define HIDP 512
#define FFN2 1020
#define NSPLIT 32

// ---------------- scratch (static device globals; allocation-free) ----------------
__device__ float g_xn  [B * C    * NPIX];
__device__ float g_buf1[B * FFN2 * NPIX];
__device__ float g_buf2[B * 3*C  * NPIX];
__device__ float g_mid [B * C    * NPIX];
__device__ float g_x2  [B * C    * NPIX];
__device__ float g_gelu[B * HIDP * NPIX];   // padded to 512 channels
__device__ float g_wout[C * HIDP];          // packed w_ffn_out [192][512]
__device__ float g_attn_part[B * HEADS * NSPLIT * HD * HD];
__device__ float g_attn[B * HEADS * HD * HD];
__device__ float g_temp [B * HEADS];
__device__ float g_vgate[B * C];
__device__ float g_invq [B * C];
__device__ float g_invk [B * C];

// ---------------- mma / cp.async helpers ----------------
__device__ __forceinline__ void mma_tf32(float* d, const unsigned* a, const unsigned* b) {
    asm volatile(
        "mma.sync.aligned.m16n8k8.row.col.f32.tf32.tf32.f32 "
        "{%0,%1,%2,%3}, {%4,%5,%6,%7}, {%8,%9}, {%0,%1,%2,%3};\n"
        : "+f"(d[0]), "+f"(d[1]), "+f"(d[2]), "+f"(d[3])
        : "r"(a[0]), "r"(a[1]), "r"(a[2]), "r"(a[3]), "r"(b[0]), "r"(b[1]));
}
__device__ __forceinline__ unsigned smem_u32(const void* p) {
    return (unsigned)__cvta_generic_to_shared(p);
}
__device__ __forceinline__ void cp16(unsigned dst, const void* src) {
    asm volatile("cp.async.cg.shared.global [%0], [%1], 16;" :: "r"(dst), "l"(src));
}
__device__ __forceinline__ void cp16p(unsigned dst, const void* src, bool pred) {
    int sz = pred ? 16 : 0;
    asm volatile("cp.async.cg.shared.global [%0], [%1], 16, %2;" :: "r"(dst), "l"(src), "r"(sz));
}
__device__ __forceinline__ void cp_commit() { asm volatile("cp.async.commit_group;"); }
template <int N>
__device__ __forceinline__ void cp_wait() { asm volatile("cp.async.wait_group %0;" :: "n"(N)); }

// ---------------- context adapters ----------------
__global__ void ctx_kernel(const float* __restrict__ ctx,
                           const float* __restrict__ ta_w1, const float* __restrict__ ta_b1,
                           const float* __restrict__ ta_w2, const float* __restrict__ ta_b2,
                           const float* __restrict__ vg_w,  const float* __restrict__ vg_b,
                           const float* __restrict__ base_temp) {
    __shared__ float sctx[CTXD];
    __shared__ float hid[HD];
    int b = blockIdx.x, t = threadIdx.x;
    sctx[t] = ctx[b * CTXD + t];
    __syncthreads();
    if (t < HD) {
        float s = ta_b1[t];
        for (int k = 0; k < CTXD; k++) s += sctx[k] * ta_w1[t * CTXD + k];
        hid[t] = fmaxf(s, 0.f);
    }
    __syncthreads();
    if (t < HEADS) {
        float s = ta_b2[t];
        for (int k = 0; k < HD; k++) s += hid[k] * ta_w2[t * HD + k];
        float f = 1.f / (1.f + expf(-s)) * 2.f + 0.5f;
        g_temp[b * HEADS + t] = base_temp[t] * f;
    }
    if (t < C) {
        float s = vg_b[t];
        for (int k = 0; k < CTXD; k++) s += sctx[k] * vg_w[t * CTXD + k];
        g_vgate[b * C + t] = 1.f / (1.f + expf(-s));
    }
}

// ---------------- weight packing + gelu pad zero ----------------
__global__ void pack_wout_kernel(const float* __restrict__ w) {
    int i = blockIdx.x * 256 + threadIdx.x;     // C*HIDP
    int o = i / HIDP, c = i % HIDP;
    g_wout[i] = (c < HID) ? w[o * HID + c] : 0.f;
}
__global__ void zero_gelu_pad_kernel() {
    int i = blockIdx.x * 256 + threadIdx.x;     // B*2*NPIX
    int b = i / (2 * NPIX), r = i % (2 * NPIX);
    g_gelu[(size_t)b * HIDP * NPIX + (size_t)HID * NPIX + r] = 0.f;
}

// ---------------- layernorm over channels (4 px / thread) ----------------
__global__ void ln_kernel(const float* __restrict__ x, const float* __restrict__ w,
                          const float* __restrict__ bias, float* __restrict__ out) {
    int tid = blockIdx.x * 256 + threadIdx.x;   // B*NPIX/4 threads
    int b = tid / (NPIX / 4), n = (tid % (NPIX / 4)) * 4;
    const float* xp = x + (size_t)b * C * NPIX + n;
    float4 s = make_float4(0.f, 0.f, 0.f, 0.f), ss = s;
    #pragma unroll 4
    for (int c = 0; c < C; c++) {
        float4 v = *reinterpret_cast<const float4*>(xp + (size_t)c * NPIX);
        s.x += v.x; s.y += v.y; s.z += v.z; s.w += v.w;
        ss.x += v.x * v.x; ss.y += v.y * v.y; ss.z += v.z * v.z; ss.w += v.w * v.w;
    }
    const float ic = 1.f / C;
    float4 mu = make_float4(s.x * ic, s.y * ic, s.z * ic, s.w * ic);
    float4 rs = make_float4(rsqrtf(ss.x * ic - mu.x * mu.x + 1e-5f),
                            rsqrtf(ss.y * ic - mu.y * mu.y + 1e-5f),
                            rsqrtf(ss.z * ic - mu.z * mu.z + 1e-5f),
                            rsqrtf(ss.w * ic - mu.w * mu.w + 1e-5f));
    float* op = out + (size_t)b * C * NPIX + n;
    #pragma unroll 4
    for (int c = 0; c < C; c++) {
        float4 v = *reinterpret_cast<const float4*>(xp + (size_t)c * NPIX);
        float wc = w[c], bc = bias[c];
        float4 o4 = make_float4((v.x - mu.x) * rs.x * wc + bc,
                                (v.y - mu.y) * rs.y * wc + bc,
                                (v.z - mu.z) * rs.z * wc + bc,
                                (v.w - mu.w) * rs.w * wc + bc);
        *reinterpret_cast<float4*>(op + (size_t)c * NPIX) = o4;
    }
}

// ---------------- pipelined tf32 GEMM: Y[b,o,n] = sum_c W[o,c] X[b,c,n] (+Res) ----------------
// Block 64(O) x 256(n), K-step 16, cp.async double buffer.
// 8 warps as 2(m) x 4(n); warp tile 32x64 = 2x8 m16n8k8.
__global__ void __launch_bounds__(256) mma_gemm(const float* __restrict__ Wm,
                                                const float* __restrict__ X,
                                                float* __restrict__ Y,
                                                const float* __restrict__ Res,
                                                int O, int Cin) {
    __shared__ float sA[2][64][20];     // [m][k] pad 20 (rows 80B, 16B-aligned chunks)
    __shared__ float sB[2][16][264];    // [k][n] pad 264 (264%32==8 -> conflict-free frags)

    int b  = blockIdx.z;
    int o0 = blockIdx.y * 64;
    int n0 = blockIdx.x * 256;
    const float* Xb = X + (size_t)b * Cin * NPIX + n0;

    int tid  = threadIdx.x;
    int warp = tid >> 5, lane = tid & 31;
    int wm = warp >> 2, wn = warp & 3;
    int mrow = lane >> 2, kq = lane & 3;

    float acc[2][8][4];
    #pragma unroll
    for (int mt = 0; mt < 2; mt++)
        #pragma unroll
        for (int nt = 0; nt < 8; nt++)
            #pragma unroll
            for (int q = 0; q < 4; q++) acc[mt][nt][q] = 0.f;

    // cp.async addressing
    int am  = tid >> 2;               // A: row m (0..63)
    int ak4 = (tid & 3) * 4;          // A: k offset {0,4,8,12}
    bool apred = (o0 + am) < O;
    const float* aSrcBase = Wm + (size_t)(o0 + am) * Cin + ak4;

    int ktiles = Cin >> 4;            // Cin is a multiple of 16 (192 or 512)

    auto LOAD = [&](int kt, int buf) {
        int c0 = kt << 4;
        cp16p(smem_u32(&sA[buf][am][ak4]), aSrcBase + c0, apred);
        #pragma unroll
        for (int i = 0; i < 4; i++) {
            int e = tid + i * 256;
            int kk = e >> 6;
            int nn = (e & 63) * 4;
            cp16(smem_u32(&sB[buf][kk][nn]), Xb + (size_t)(c0 + kk) * NPIX + nn);
        }
        cp_commit();
    };

    LOAD(0, 0);
    for (int kt = 0; kt < ktiles; kt++) {
        int cur = kt & 1;
        if (kt + 1 < ktiles) { LOAD(kt + 1, cur ^ 1); cp_wait<1>(); }
        else cp_wait<0>();
        __syncthreads();

        const unsigned (*A)[20]  = reinterpret_cast<const unsigned (*)[20]>(sA[cur]);
        const unsigned (*Bs)[264] = reinterpret_cast<const unsigned (*)[264]>(sB[cur]);
        #pragma unroll
        for (int ks = 0; ks < 2; ks++) {
            const int k0 = ks * 8;
            unsigned afr[2][4], bfr[8][2];
            #pragma unroll
            for (int mt = 0; mt < 2; mt++) {
                int m = wm * 32 + mt * 16 + mrow;
                afr[mt][0] = A[m    ][k0 + kq];
                afr[mt][1] = A[m + 8][k0 + kq];
                afr[mt][2] = A[m    ][k0 + kq + 4];
                afr[mt][3] = A[m + 8][k0 + kq + 4];
            }
            #pragma unroll
            for (int nt = 0; nt < 8; nt++) {
                int n = wn * 64 + nt * 8 + mrow;
                bfr[nt][0] = Bs[k0 + kq    ][n];
                bfr[nt][1] = Bs[k0 + kq + 4][n];
            }
            #pragma unroll
            for (int mt = 0; mt < 2; mt++)
                #pragma unroll
                for (int nt = 0; nt < 8; nt++)
                    mma_tf32(acc[mt][nt], afr[mt], bfr[nt]);
        }
        __syncthreads();
    }

    size_t base = (size_t)b * O * NPIX;
    #pragma unroll
    for (int mt = 0; mt < 2; mt++) {
        #pragma unroll
        for (int nt = 0; nt < 8; nt++) {
            int ncol = n0 + wn * 64 + nt * 8 + 2 * kq;
            int r0 = o0 + wm * 32 + mt * 16 + mrow;
            if (r0 < O) {
                size_t off = base + (size_t)r0 * NPIX + ncol;
                float2 rr = Res ? *reinterpret_cast<const float2*>(Res + off)
                                : make_float2(0.f, 0.f);
                *reinterpret_cast<float2*>(Y + off) =
                    make_float2(acc[mt][nt][0] + rr.x, acc[mt][nt][1] + rr.y);
            }
            int r1 = r0 + 8;
            if (r1 < O) {
                size_t off = base + (size_t)r1 * NPIX + ncol;
                float2 rr = Res ? *reinterpret_cast<const float2*>(Res + off)
                                : make_float2(0.f, 0.f);
                *reinterpret_cast<float2*>(Y + off) =
                    make_float2(acc[mt][nt][2] + rr.x, acc[mt][nt][3] + rr.y);
            }
        }
    }
}

// ---------------- depthwise 3x3 (4 px / thread) ----------------
__device__ __forceinline__ void dw3x3_v4(const float* __restrict__ ip,
                                         const float* __restrict__ wp,
                                         int y, int x, float* acc) {
    acc[0] = acc[1] = acc[2] = acc[3] = 0.f;
    #pragma unroll
    for (int ky = 0; ky < 3; ky++) {
        int yy = y + ky - 1;
        if (yy < 0 || yy >= HGT) continue;
        const float* row = ip + yy * WID + x;
        float4 m = *reinterpret_cast<const float4*>(row);
        float left  = (x > 0)   ? row[-1] : 0.f;
        float right = (x < 124) ? row[4]  : 0.f;
        float w0 = wp[ky * 3 + 0], w1 = wp[ky * 3 + 1], w2 = wp[ky * 3 + 2];
        acc[0] += left * w0 + m.x * w1 + m.y * w2;
        acc[1] += m.x  * w0 + m.y * w1 + m.z * w2;
        acc[2] += m.y  * w0 + m.z * w1 + m.w * w2;
        acc[3] += m.z  * w0 + m.w * w1 + right * w2;
    }
}

__global__ void dwconv_kernel(const float* __restrict__ in, const float* __restrict__ w,
                              float* __restrict__ out, int CH, int inStrideB, int outStrideB) {
    int idx = blockIdx.x * 256 + threadIdx.x;   // B*CH*NPIX/4
    int n = (idx & (NPIX / 4 - 1)) * 4;
    int bc = idx >> 12;
    int c = bc % CH, b = bc / CH;
    int y = n >> 7, x = n & 127;
    const float* ip = in + (size_t)b * inStrideB + (size_t)c * NPIX;
    float acc[4];
    dw3x3_v4(ip, w + c * 9, y, x, acc);
    *reinterpret_cast<float4*>(out + (size_t)b * outStrideB + (size_t)c * NPIX + n) =
        make_float4(acc[0], acc[1], acc[2], acc[3]);
}

// ---------------- fused FFN dwconv + gelu gate (4 px / thread) ----------------
__global__ void dwgelu_kernel(const float* __restrict__ in, const float* __restrict__ w,
                              float* __restrict__ outg) {
    int idx = blockIdx.x * 256 + threadIdx.x;   // B*HID*NPIX/4
    int n = (idx & (NPIX / 4 - 1)) * 4;
    int bc = idx >> 12;
    int c = bc % HID, b = bc / HID;
    int y = n >> 7, x = n & 127;
    const float* base = in + (size_t)b * FFN2 * NPIX;
    float a1[4], a2[4];
    dw3x3_v4(base + (size_t)c * NPIX, w + c * 9, y, x, a1);
    dw3x3_v4(base + (size_t)(c + HID) * NPIX, w + (c + HID) * 9, y, x, a2);
    float4 o4;
    float* op = &o4.x;
    #pragma unroll
    for (int j = 0; j < 4; j++) {
        float g = 0.5f * a1[j] * (1.f + erff(a1[j] * 0.70710678118654752f));
        op[j] = g * a2[j];
    }
    *reinterpret_cast<float4*>(outg + (size_t)b * HIDP * NPIX + (size_t)c * NPIX + n) = o4;
}

// ---------------- q/k L2-norm over spatial ----------------
__global__ void norm_kernel() {
    int idx = blockIdx.x;              // 0 .. 2*B*C-1
    int isK = idx >= B * C;
    int lin = isK ? idx - B * C : idx;
    int b = lin / C, c = lin % C;
    const float* p = g_buf2 + (size_t)b * (3 * C) * NPIX + (size_t)((isK ? C : 0) + c) * NPIX;
    float ss = 0.f;
    for (int n = threadIdx.x * 4; n < NPIX; n += 1024) {
        float4 v = *reinterpret_cast<const float4*>(p + n);
        ss += v.x * v.x + v.y * v.y + v.z * v.z + v.w * v.w;
    }
    __shared__ float red[256];
    red[threadIdx.x] = ss; __syncthreads();
    for (int s = 128; s > 0; s >>= 1) {
        if (threadIdx.x < s) red[threadIdx.x] += red[threadIdx.x + s];
        __syncthreads();
    }
    if (threadIdx.x == 0) {
        float inv = 1.f / fmaxf(sqrtf(red[0]), 1e-12f);
        (isK ? g_invk : g_invq)[b * C + c] = inv;
    }
}

// ---------------- attention gram partials ----------------
__global__ void attn_part_kernel() {
    __shared__ float sQ[HD][33], sK[HD][33];
    int bh = blockIdx.x / NSPLIT, sp = blockIdx.x % NSPLIT;
    int b = bh / HEADS, h = bh % HEADS;
    const float* qb = g_buf2 + (size_t)b * (3 * C) * NPIX + (size_t)(h * HD) * NPIX;
    const float* kb = qb + (size_t)C * NPIX;
    int t = threadIdx.x;
    int i0 = (t >> 4) * 3, j0 = (t & 15) * 3;
    float acc[3][3];
    #pragma unroll
    for (int a = 0; a < 3; a++)
        #pragma unroll
        for (int c2 = 0; c2 < 3; c2++) acc[a][c2] = 0.f;
    int n0 = sp * (NPIX / NSPLIT);
    for (int ch = 0; ch < NPIX / NSPLIT; ch += 32) {
        for (int e = t; e < HD * 32; e += 256) {
            int i = e >> 5, nn = e & 31;
            sQ[i][nn] = qb[(size_t)i * NPIX + n0 + ch + nn];
            sK[i][nn] = kb[(size_t)i * NPIX + n0 + ch + nn];
        }
        __syncthreads();
        #pragma unroll 4
        for (int kk = 0; kk < 32; kk++) {
            float qa[3], ka[3];
            #pragma unroll
            for (int a = 0; a < 3; a++) { qa[a] = sQ[i0 + a][kk]; ka[a] = sK[j0 + a][kk]; }
            #pragma unroll
            for (int a = 0; a < 3; a++)
                #pragma unroll
                for (int c2 = 0; c2 < 3; c2++) acc[a][c2] += qa[a] * ka[c2];
        }
        __syncthreads();
    }
    float* outp = g_attn_part + (size_t)blockIdx.x * HD * HD;
    #pragma unroll
    for (int a = 0; a < 3; a++)
        #pragma unroll
        for (int c2 = 0; c2 < 3; c2++) outp[(i0 + a) * HD + j0 + c2] = acc[a][c2];
}

// ---------------- softmax + fold norms/scale/temp/vgate ----------------
__global__ void softmax_kernel() {
    __shared__ float row[HD];
    __shared__ float mx, sm;
    int rid = blockIdx.x;
    int i  = rid % HD;
    int bh = rid / HD;
    int b = bh / HEADS, h = bh % HEADS;
    int t = threadIdx.x;
    const float scale = 0.14433756729740643f;   // 48^-0.5
    if (t < HD) {
        float s = 0.f;
        const float* pp = g_attn_part + (size_t)bh * NSPLIT * HD * HD + i * HD + t;
        for (int sp = 0; sp < NSPLIT; sp++) s += pp[(size_t)sp * HD * HD];
        row[t] = s * g_invq[b * C + h * HD + i] * g_invk[b * C + h * HD + t]
                   * scale * g_temp[b * HEADS + h];
    }
    __syncthreads();
    if (t == 0) { float m = -1e30f; for (int j = 0; j < HD; j++) m = fmaxf(m, row[j]); mx = m; }
    __syncthreads();
    if (t < HD) row[t] = expf(row[t] - mx);
    __syncthreads();
    if (t == 0) { float s2 = 0.f; for (int j = 0; j < HD; j++) s2 += row[j]; sm = s2; }
    __syncthreads();
    if (t < HD)
        g_attn[(size_t)bh * HD * HD + i * HD + t] = row[t] / sm * g_vgate[b * C + h * HD + t];
}

// ---------------- out_global = attn @ v, accumulated onto g_mid ----------------
__global__ void og_kernel() {
    __shared__ float sA[HD * HD];
    __shared__ float sV[HD][65];
    int bh = blockIdx.y;
    int b = bh / HEADS, h = bh % HEADS;
    int n0 = blockIdx.x * 64;
    const float* vb = g_buf2 + (size_t)b * (3 * C) * NPIX + (size_t)(2 * C + h * HD) * NPIX;
    int t = threadIdx.x;
    for (int e = t; e < HD * HD; e += 256) sA[e] = g_attn[(size_t)bh * HD * HD + e];
    for (int e = t; e < HD * 64; e += 256) {
        int j = e >> 6, n = e & 63;
        sV[j][n] = vb[(size_t)j * NPIX + n0 + n];
    }
    __syncthreads();
    int i0 = (t >> 4) * 3;
    int nl = (t & 15) * 4;
    float acc[3][4];
    #pragma unroll
    for (int a = 0; a < 3; a++)
        #pragma unroll
        for (int q = 0; q < 4; q++) acc[a][q] = 0.f;
    #pragma unroll 4
    for (int j = 0; j < HD; j++) {
        float vv[4];
        #pragma unroll
        for (int q = 0; q < 4; q++) vv[q] = sV[j][nl + q];
        #pragma unroll
        for (int a = 0; a < 3; a++) {
            float aa = sA[(i0 + a) * HD + j];
            #pragma unroll
            for (int q = 0; q < 4; q++) acc[a][q] += aa * vv[q];
        }
    }
    float* op = g_mid + (size_t)b * C * NPIX + (size_t)(h * HD) * NPIX + n0;
    #pragma unroll
    for (int a = 0; a < 3; a++)
        #pragma unroll
        for (int q = 0; q < 4; q++)
            op[(size_t)(i0 + a) * NPIX + nl + q] += acc[a][q];
}

// ---------------- launch ----------------
extern "C" void kernel_launch(void* const* d_in, const int* in_sizes, int n_in,
                              void* d_out, int out_size) {
    const float* x        = (const float*)d_in[0];
    const float* ctx      = (const float*)d_in[1];
    const float* ln1_w    = (const float*)d_in[2];
    const float* ln1_b    = (const float*)d_in[3];
    const float* ln2_w    = (const float*)d_in[4];
    const float* ln2_b    = (const float*)d_in[5];
    const float* w_qkv    = (const float*)d_in[6];
    const float* w_qkv_dw = (const float*)d_in[7];
    const float* w_proj   = (const float*)d_in[8];
    const float* base_temp= (const float*)d_in[9];
    const float* ta_w1    = (const float*)d_in[10];
    const float* ta_b1    = (const float*)d_in[11];
    const float* ta_w2    = (const float*)d_in[12];
    const float* ta_b2    = (const float*)d_in[13];
    const float* vg_w     = (const float*)d_in[14];
    const float* vg_b     = (const float*)d_in[15];
    const float* w_local  = (const float*)d_in[16];
    const float* w_ffn_in = (const float*)d_in[17];
    const float* w_ffn_dw = (const float*)d_in[18];
    const float* w_ffn_out= (const float*)d_in[19];
    float* out = (float*)d_out;

    float *p_xn, *p_buf1, *p_buf2, *p_mid, *p_x2, *p_gelu, *p_wout;
    cudaGetSymbolAddress((void**)&p_xn,   g_xn);
    cudaGetSymbolAddress((void**)&p_buf1, g_buf1);
    cudaGetSymbolAddress((void**)&p_buf2, g_buf2);
    cudaGetSymbolAddress((void**)&p_mid,  g_mid);
    cudaGetSymbolAddress((void**)&p_x2,   g_x2);
    cudaGetSymbolAddress((void**)&p_gelu, g_gelu);
    cudaGetSymbolAddress((void**)&p_wout, g_wout);

    ctx_kernel<<<B, 256>>>(ctx, ta_w1, ta_b1, ta_w2, ta_b2, vg_w, vg_b, base_temp);
    pack_wout_kernel<<<(C * HIDP) / 256, 256>>>(w_ffn_out);
    zero_gelu_pad_kernel<<<(B * 2 * NPIX) / 256, 256>>>();

    ln_kernel<<<(B * NPIX / 4) / 256, 256>>>(x, ln1_w, ln1_b, p_xn);
    // qkv conv1x1 (576 x 192)
    mma_gemm<<<dim3(NPIX / 256, (3 * C) / 64, B), 256>>>(w_qkv, p_xn, p_buf1, nullptr, 3 * C, C);
    // qkv dwconv
    dwconv_kernel<<<(B * 3 * C * NPIX / 4) / 256, 256>>>(p_buf1, w_qkv_dw, p_buf2, 3 * C,
                                                         3 * C * NPIX, 3 * C * NPIX);
    norm_kernel<<<2 * B * C, 256>>>();
    attn_part_kernel<<<B * HEADS * NSPLIT, 256>>>();
    softmax_kernel<<<B * HEADS * HD, 64>>>();
    dwconv_kernel<<<(B * C * NPIX / 4) / 256, 256>>>(p_buf2 + (size_t)2 * C * NPIX, w_local, p_mid,
                                                     C, 3 * C * NPIX, C * NPIX);
    og_kernel<<<dim3(NPIX / 64, B * HEADS), 256>>>();
    // proj conv1x1 + residual(x)
    mma_gemm<<<dim3(NPIX / 256, C / 64, B), 256>>>(w_proj, p_mid, p_x2, x, C, C);
    ln_kernel<<<(B * NPIX / 4) / 256, 256>>>(p_x2, ln2_w, ln2_b, p_xn);
    // ffn_in conv1x1 (1020 x 192)
    mma_gemm<<<dim3(NPIX / 256, (FFN2 + 63) / 64, B), 256>>>(w_ffn_in, p_xn, p_buf1, nullptr, FFN2, C);
    // fused ffn dwconv + gelu gate
    dwgelu_kernel<<<(B * HID * NPIX / 4) / 256, 256>>>(p_buf1, w_ffn_dw, p_gelu);
    // ffn_out conv1x1 (192 x 512 padded) + residual(g_x2)
    mma_gemm<<<dim3(NPIX / 256, C / 64, B), 256>>>(p_wout, p_gelu, out, p_x2, C, HIDP);
}